// round 16
// baseline (speedup 1.0000x reference)
#include <cuda_runtime.h>
#include <cuda_fp16.h>
#include <cstdint>

#define EMBED 384
#define IMG_HW 224
#define GRID_HW 14
#define NPATCH 196
#define M_TOTAL 12544
#define K_TOTAL 768
#define CHAN_STRIDE 50176
#define M_CTA 64
#define G_CTAS 196               // M_TOTAL / 64
#define NCHUNK 24
#define THREADS 512

// B: fp16, chunk-major, ldmatrix-swizzled: halfs c*12288 + n*32 + (seg^((n>>1)&3))*8 + k7
__device__ __half g_wh[NCHUNK * EMBED * 32];

#define B_CH_BYTES 24576         // 384*64
#define A_BUF_BYTES 4096         // 64*64
// ---- dynamic smem layout (bytes) ----
#define SM_B0    0               // 3 B stages (73728)
#define SM_A0    73728           // 2 A bufs (8192)
#define SM_BIAS  81920
#define SM_GAMMA 83456
#define SM_BETA  84992
#define SM_RSUM  86528           // 64 f
#define SM_RSQ   86784
#define SM_MU    87040
#define SM_RS    87296
#define SM_MBAR  87552           // 3 x 8B (pad 64)
#define SM_HIST  87616           // 64 rows x 32 bins x int = 8192
#define SMEM_TOTAL 95808

__device__ __forceinline__ uint32_t smem_u32(const void* p) {
    uint32_t a;
    asm("{ .reg .u64 t; cvta.to.shared.u64 t, %1; cvt.u32.u64 %0, t; }"
        : "=r"(a) : "l"(p));
    return a;
}
__device__ __forceinline__ uint32_t pack2(float a, float b) {
    __half2 h = __floats2half2_rn(a, b);
    return *reinterpret_cast<uint32_t*>(&h);
}

#define MBAR_INIT(addr, cnt) \
    asm volatile("mbarrier.init.shared.b64 [%0], %1;" :: "r"(addr), "r"(cnt) : "memory")
#define MBAR_EXPECT_TX(addr, bytes) \
    asm volatile("mbarrier.arrive.expect_tx.shared.b64 _, [%0], %1;" \
                 :: "r"(addr), "r"(bytes) : "memory")
#define BULK_CP(dst, src, bytes, mbar) \
    asm volatile("cp.async.bulk.shared::cta.global.mbarrier::complete_tx::bytes " \
                 "[%0], [%1], %2, [%3];" \
                 :: "r"(dst), "l"(src), "r"(bytes), "r"(mbar) : "memory")
#define MBAR_WAIT(addr, par) do {                                              \
    uint32_t _m = (addr); uint32_t _p = (par); uint32_t _d;                    \
    asm volatile("{\n\t.reg .pred p;\n\t"                                      \
        "mbarrier.try_wait.parity.acquire.cta.shared::cta.b64 p, [%1], %2;\n\t"\
        "selp.b32 %0, 1, 0, p;\n\t}"                                           \
        : "=r"(_d) : "r"(_m), "r"(_p) : "memory");                             \
    if (!_d) {                                                                 \
        asm volatile("{\n\t.reg .pred P1;\n\t"                                 \
            "W%=:\n\t"                                                         \
            "mbarrier.try_wait.parity.acquire.cta.shared::cta.b64 P1, [%0], %1, 0x989680;\n\t" \
            "@P1 bra.uni D%=;\n\t"                                             \
            "bra.uni W%=;\n\t"                                                 \
            "D%=:\n\t}" :: "r"(_m), "r"(_p) : "memory");                       \
    }                                                                          \
} while (0)

#define LDSM4(r0, r1, r2, r3, a) \
    asm volatile("ldmatrix.sync.aligned.m8n8.x4.shared.b16 {%0,%1,%2,%3}, [%4];" \
                 : "=r"(r0), "=r"(r1), "=r"(r2), "=r"(r3) : "r"(a))

#define MMA16816(d, a0, a1, a2, a3, b0, b1) \
    asm volatile("mma.sync.aligned.m16n8k16.row.col.f32.f16.f16.f32 " \
                 "{%0,%1,%2,%3}, {%4,%5,%6,%7}, {%8,%9}, {%0,%1,%2,%3};" \
                 : "+f"((d)[0]), "+f"((d)[1]), "+f"((d)[2]), "+f"((d)[3]) \
                 : "r"(a0), "r"(a1), "r"(a2), "r"(a3), "r"(b0), "r"(b1))

// ---------------------------------------------------------------------------
// W fp16 convert: 73728 float4s, 288 blocks x 256 thr x 1.
// ---------------------------------------------------------------------------
__global__ __launch_bounds__(256) void wcvt_kernel(const float* __restrict__ w) {
    int i = blockIdx.x * 256 + threadIdx.x;
    int n = i / 192;
    int k = (i % 192) * 4;
    float4 v = *(const float4*)(w + (size_t)n * K_TOTAL + k);
    int c = k >> 5;
    int kin = k & 31;
    int phys = (kin >> 3) ^ ((n >> 1) & 3);
    uint32_t* dst = (uint32_t*)(g_wh + c * 12288 + n * 32 + phys * 8 + (kin & 7));
    dst[0] = pack2(v.x, v.y);
    dst[1] = pack2(v.z, v.w);
}

// ---------------------------------------------------------------------------
// Fused GEMM + bias + LayerNorm + entropy. One block per 64 M-rows.
// 512 threads = 16 warps (2 m-groups x 8 n-warps), warp tile 32x48.
// K chunks channel-interleaved (i -> c=(i%3)*8+i/3) for the entropy carry.
// ---------------------------------------------------------------------------
__global__ __launch_bounds__(THREADS, 1) void fused_kernel(
    const float* __restrict__ img, const float* __restrict__ bias,
    const float* __restrict__ gamma, const float* __restrict__ beta,
    float* __restrict__ out, float* __restrict__ ent) {
    extern __shared__ char smem[];
    const int bid = blockIdx.x;
    const int tid = threadIdx.x;
    const int wid = tid >> 5;
    const int lid = tid & 31;
    const int wn = wid & 7;          // n-warp 0..7 (48 cols each)
    const int wm = wid >> 3;         // m-group 0..1 (32 rows each)
    const int bm = bid;
    const uint32_t sbase = smem_u32(smem);
    const int qr = lid >> 2;
    const int qc = lid & 3;

    int* hist = (int*)(smem + SM_HIST);
    #pragma unroll
    for (int z = 0; z < 4; z++) hist[tid + THREADS * z] = 0;

    if (tid < 64) {
        ((float*)(smem + SM_RSUM))[tid] = 0.0f;
        ((float*)(smem + SM_RSQ))[tid]  = 0.0f;
    }
    if (tid >= 64 && tid < 64 + 96) {
        int i4 = tid - 64;
        ((float4*)(smem + SM_BIAS))[i4]  = ((const float4*)bias)[i4];
        ((float4*)(smem + SM_GAMMA))[i4] = ((const float4*)gamma)[i4];
        ((float4*)(smem + SM_BETA))[i4]  = ((const float4*)beta)[i4];
    }
    if (tid == 0) {
        // Stage s starts with chunk c_seq[s] = s*8 (channel s, group 0).
        #pragma unroll
        for (int s = 0; s < 3; s++) {
            MBAR_INIT(sbase + SM_MBAR + 8 * s, 1);
            MBAR_EXPECT_TX(sbase + SM_MBAR + 8 * s, B_CH_BYTES);
            BULK_CP(sbase + s * B_CH_BYTES,
                    (const char*)g_wh + (size_t)(s * 8) * B_CH_BYTES, B_CH_BYTES,
                    sbase + SM_MBAR + 8 * s);
        }
    }

    // A gather geometry: 1 float4 per thread per chunk (512 = 64 rows x 8 slots).
    const int arow = tid >> 3;       // 0..63
    const int aj = tid & 7;
    const float* abase;
    {
        int m = bm * M_CTA + arow;
        abase = img + (size_t)((m / NPATCH) * 3) * CHAN_STRIDE
              + (size_t)(((m % NPATCH) / GRID_HW) * 16) * IMG_HW
              + ((m % NPATCH) % GRID_HW) * 16;
    }
    const uint32_t adst = arow * 64 + (((aj >> 1) ^ ((arow >> 1) & 3)) << 4)
                        + (aj & 1) * 8;
    // chunk c = ph*8 + grp  ->  k = ph*256 + grp*32 + 4*aj
    auto aoff = [&](int ph, int grp) -> size_t {
        int pix = grp * 32 + 4 * aj;
        return (size_t)ph * CHAN_STRIDE + (pix >> 4) * IMG_HW + (pix & 15);
    };

    // Prologue: A(i=0: ph0,g0) -> buf0 + entropy carry; A(i=1: ph1,g0) -> regs.
    float4 carry, areg;
    {
        float4 v = *(const float4*)(abase + aoff(0, 0));
        *(uint2*)(smem + SM_A0 + adst) = make_uint2(pack2(v.x, v.y), pack2(v.z, v.w));
        carry = v;
        areg = *(const float4*)(abase + aoff(1, 0));
    }
    __syncthreads();

    float acc[48];
    #pragma unroll
    for (int i = 0; i < 48; i++) acc[i] = 0.0f;

    // lane geometry (ldmatrix)
    const int a_row = ((lid >> 3) & 1) * 8 + (lid & 7);
    const int a_kbit = lid >> 4;
    const int b_noff = ((lid >> 4) & 1) * 8 + (lid & 7);
    const int b_segbit = (lid >> 3) & 1;
    const int xr = (lid & 7) >> 1;

    // j = i+2 counters for A prefetch (ph2, grp2), current-c counters for B.
    int ph2 = 2, grp2 = 0;
    int phc = 0, grpc = 0;
    int s = 0, par = 0, c3 = 0;

    for (int i = 0; i < NCHUNK; i++) {
        MBAR_WAIT(sbase + SM_MBAR + 8 * s, par);

        // Store A(i+1) + entropy step (j = i+1); prefetch A(i+2).
        if (i + 1 < NCHUNK) {
            *(uint2*)(smem + SM_A0 + ((i + 1) & 1) * A_BUF_BYTES + adst) =
                make_uint2(pack2(areg.x, areg.y), pack2(areg.z, areg.w));
            const int jph = (i + 1) % 3;
            if (jph == 0) {
                carry = areg;
            } else if (jph == 1) {
                carry.x += areg.x; carry.y += areg.y;
                carry.z += areg.z; carry.w += areg.w;
            } else {
                float g0 = (carry.x + areg.x) * (1.0f / 3.0f);
                float g1 = (carry.y + areg.y) * (1.0f / 3.0f);
                float g2 = (carry.z + areg.z) * (1.0f / 3.0f);
                float g3 = (carry.w + areg.w) * (1.0f / 3.0f);
                int* hrow = hist + arow * 32;
                atomicAdd(hrow + (int)fminf(fmaxf(g0 * 31.0f, 0.0f), 31.0f), 1);
                atomicAdd(hrow + (int)fminf(fmaxf(g1 * 31.0f, 0.0f), 31.0f), 1);
                atomicAdd(hrow + (int)fminf(fmaxf(g2 * 31.0f, 0.0f), 31.0f), 1);
                atomicAdd(hrow + (int)fminf(fmaxf(g3 * 31.0f, 0.0f), 31.0f), 1);
            }
            if (i + 2 < NCHUNK) {
                areg = *(const float4*)(abase + aoff(ph2, grp2));
                if (++ph2 == 3) { ph2 = 0; grp2++; }
            }
        }

        const uint32_t Bst = sbase + s * B_CH_BYTES;
        const uint32_t Ast = sbase + SM_A0 + (i & 1) * A_BUF_BYTES;
        #pragma unroll
        for (int sh = 0; sh < 2; sh++) {
            uint32_t bf[3][4];
            const int sg = (2 * sh + b_segbit) ^ xr;
            #pragma unroll
            for (int tp = 0; tp < 3; tp++) {
                int n = 48 * wn + 16 * tp + b_noff;
                LDSM4(bf[tp][0], bf[tp][1], bf[tp][2], bf[tp][3],
                      Bst + n * 64 + sg * 16);
            }
            const int aseg = (2 * sh + a_kbit) ^ xr;
            #pragma unroll
            for (int ii = 0; ii < 2; ii++) {
                uint32_t a0, a1, a2, a3;
                LDSM4(a0, a1, a2, a3,
                      Ast + (32 * wm + 16 * ii + a_row) * 64 + aseg * 16);
                #pragma unroll
                for (int tp = 0; tp < 3; tp++) {
                    MMA16816(acc + (ii * 6 + 2 * tp) * 4, a0, a1, a2, a3,
                             bf[tp][0], bf[tp][1]);
                    MMA16816(acc + (ii * 6 + 2 * tp + 1) * 4, a0, a1, a2, a3,
                             bf[tp][2], bf[tp][3]);
                }
            }
        }
        __syncthreads();
        // Refill stage s with the next chunk of the SAME channel: c_cur + 1.
        if (tid == 0 && i + 3 < NCHUNK) {
            const int cnext = phc * 8 + grpc + 1;
            MBAR_EXPECT_TX(sbase + SM_MBAR + 8 * s, B_CH_BYTES);
            BULK_CP(sbase + s * B_CH_BYTES,
                    (const char*)g_wh + (size_t)cnext * B_CH_BYTES,
                    B_CH_BYTES, sbase + SM_MBAR + 8 * s);
        }
        if (++phc == 3) { phc = 0; grpc++; }
        if (++s == 3) { s = 0; }
        if (++c3 == 3) { c3 = 0; par ^= 1; }
    }

    // ---------------- fused LayerNorm epilogue ----------------
    float* rsum = (float*)(smem + SM_RSUM);
    float* rsq  = (float*)(smem + SM_RSQ);
    const float* sbias = (const float*)(smem + SM_BIAS);

    float2 bs2[6];
    #pragma unroll
    for (int t = 0; t < 6; t++)
        bs2[t] = *(const float2*)&sbias[48 * wn + 8 * t + 2 * qc];

    #pragma unroll
    for (int i = 0; i < 2; i++) {
        float s0 = 0, q0 = 0, s1 = 0, q1 = 0;
        #pragma unroll
        for (int t = 0; t < 6; t++) {
            float* d = acc + (i * 6 + t) * 4;
            d[0] += bs2[t].x; d[1] += bs2[t].y;
            d[2] += bs2[t].x; d[3] += bs2[t].y;
            s0 += d[0] + d[1]; q0 += d[0] * d[0] + d[1] * d[1];
            s1 += d[2] + d[3]; q1 += d[2] * d[2] + d[3] * d[3];
        }
        #pragma unroll
        for (int o = 1; o <= 2; o <<= 1) {
            s0 += __shfl_xor_sync(0xffffffffu, s0, o);
            q0 += __shfl_xor_sync(0xffffffffu, q0, o);
            s1 += __shfl_xor_sync(0xffffffffu, s1, o);
            q1 += __shfl_xor_sync(0xffffffffu, q1, o);
        }
        if (qc == 0) {
            const int r = 32 * wm + 16 * i + qr;
            atomicAdd(&rsum[r], s0);
            atomicAdd(&rsq[r], q0);
            atomicAdd(&rsum[r + 8], s1);
            atomicAdd(&rsq[r + 8], q1);
        }
    }
    __syncthreads();

    // Entropy reduction: 16 warps x 4 rows; lane = bin.
    {
        #pragma unroll
        for (int rr = 0; rr < 4; rr++) {
            const int r = wid * 4 + rr;
            float p = (float)hist[r * 32 + lid] * (1.0f / 256.0f);
            float t = p * log2f(p + 1e-10f);
            #pragma unroll
            for (int o = 16; o; o >>= 1) t += __shfl_xor_sync(0xffffffffu, t, o);
            if (lid == 0) ent[bm * M_CTA + r] = -t * 0.2f;
        }
    }

    float* smu = (float*)(smem + SM_MU);
    float* srs = (float*)(smem + SM_RS);
    if (tid < 64) {
        float mu = rsum[tid] * (1.0f / EMBED);
        float vv = rsq[tid] * (1.0f / EMBED) - mu * mu;
        smu[tid] = mu;
        srs[tid] = rsqrtf(fmaxf(vv, 0.0f) + 1e-5f);
    }
    __syncthreads();

    const float* sg = (const float*)(smem + SM_GAMMA);
    const float* sb = (const float*)(smem + SM_BETA);
    float2 g2[6], be2[6];
    #pragma unroll
    for (int t = 0; t < 6; t++) {
        g2[t]  = *(const float2*)&sg[48 * wn + 8 * t + 2 * qc];
        be2[t] = *(const float2*)&sb[48 * wn + 8 * t + 2 * qc];
    }

    #pragma unroll
    for (int i = 0; i < 2; i++) {
        const int r0 = 32 * wm + 16 * i + qr;
        const float mu0 = smu[r0], rs0 = srs[r0];
        const float mu1 = smu[r0 + 8], rs1 = srs[r0 + 8];
        float* o0 = out + (size_t)(bm * M_CTA + r0) * EMBED + 48 * wn + 2 * qc;
        float* o1 = o0 + 8 * (size_t)EMBED;
        #pragma unroll
        for (int t = 0; t < 6; t++) {
            float* d = acc + (i * 6 + t) * 4;
            float2 w0, w1;
            w0.x = (d[0] - mu0) * rs0 * g2[t].x + be2[t].x;
            w0.y = (d[1] - mu0) * rs0 * g2[t].y + be2[t].y;
            w1.x = (d[2] - mu1) * rs1 * g2[t].x + be2[t].x;
            w1.y = (d[3] - mu1) * rs1 * g2[t].y + be2[t].y;
            *(float2*)(o0 + 8 * t) = w0;
            *(float2*)(o1 + 8 * t) = w1;
        }
    }
}

// ---------------------------------------------------------------------------
extern "C" void kernel_launch(void* const* d_in, const int* in_sizes, int n_in,
                              void* d_out, int out_size) {
    const float* images = (const float*)d_in[0];
    const float* proj_w = (const float*)d_in[1];
    const float* proj_b = (const float*)d_in[2];
    const float* ln_g   = (const float*)d_in[3];
    const float* ln_b   = (const float*)d_in[4];
    float* out = (float*)d_out;

    float* x   = out;
    float* ent = out + (size_t)M_TOTAL * EMBED;

    cudaFuncSetAttribute(fused_kernel,
                         cudaFuncAttributeMaxDynamicSharedMemorySize, SMEM_TOTAL);

    wcvt_kernel<<<288, 256>>>(proj_w);
    fused_kernel<<<G_CTAS, THREADS, SMEM_TOTAL>>>(images, proj_b, ln_g, ln_b,
                                                  x, ent);
}

// round 17
// speedup vs baseline: 1.3613x; 1.3613x over previous
#include <cuda_runtime.h>
#include <cuda_fp16.h>
#include <cstdint>

#define EMBED 384
#define IMG_HW 224
#define GRID_HW 14
#define NPATCH 196
#define M_TOTAL 12544
#define K_TOTAL 768
#define CHAN_STRIDE 50176
#define M_CTA 32
#define G_CTAS 392               // M_TOTAL / 32
#define NITER 12                 // 12 iterations x K=64

// B: fp16, chunk-major, ldmatrix-swizzled: halfs c*12288 + n*32 + (seg^((n>>1)&3))*8 + k7
__device__ __half g_wh[24 * EMBED * 32];

#define B_IT_BYTES 49152         // 2 chunks x 24576
#define A_IT_BYTES 4096          // 2 chunks x 2048
// ---- dynamic smem layout (bytes) ----
#define SM_B0    0               // 2 B stages x 49152 = 98304
#define SM_A0    98304           // 2 A bufs x 4096 = 8192
#define SM_RSUM  106496          // 32 f
#define SM_RSQ   106624
#define SM_MU    106752
#define SM_RS    106880
#define SM_MBAR  107008          // 2 x 8B (pad 64)
#define SM_HIST  107072          // 32 rows x 32 bins x int = 4096
#define SMEM_TOTAL 111168

__device__ __forceinline__ uint32_t smem_u32(const void* p) {
    uint32_t a;
    asm("{ .reg .u64 t; cvta.to.shared.u64 t, %1; cvt.u32.u64 %0, t; }"
        : "=r"(a) : "l"(p));
    return a;
}
__device__ __forceinline__ uint32_t pack2(float a, float b) {
    __half2 h = __floats2half2_rn(a, b);
    return *reinterpret_cast<uint32_t*>(&h);
}

#define MBAR_INIT(addr, cnt) \
    asm volatile("mbarrier.init.shared.b64 [%0], %1;" :: "r"(addr), "r"(cnt) : "memory")
#define MBAR_EXPECT_TX(addr, bytes) \
    asm volatile("mbarrier.arrive.expect_tx.shared.b64 _, [%0], %1;" \
                 :: "r"(addr), "r"(bytes) : "memory")
#define BULK_CP(dst, src, bytes, mbar) \
    asm volatile("cp.async.bulk.shared::cta.global.mbarrier::complete_tx::bytes " \
                 "[%0], [%1], %2, [%3];" \
                 :: "r"(dst), "l"(src), "r"(bytes), "r"(mbar) : "memory")
#define MBAR_WAIT(addr, par) do {                                              \
    uint32_t _m = (addr); uint32_t _p = (par); uint32_t _d;                    \
    asm volatile("{\n\t.reg .pred p;\n\t"                                      \
        "mbarrier.try_wait.parity.acquire.cta.shared::cta.b64 p, [%1], %2;\n\t"\
        "selp.b32 %0, 1, 0, p;\n\t}"                                           \
        : "=r"(_d) : "r"(_m), "r"(_p) : "memory");                             \
    if (!_d) {                                                                 \
        asm volatile("{\n\t.reg .pred P1;\n\t"                                 \
            "W%=:\n\t"                                                         \
            "mbarrier.try_wait.parity.acquire.cta.shared::cta.b64 P1, [%0], %1, 0x989680;\n\t" \
            "@P1 bra.uni D%=;\n\t"                                             \
            "bra.uni W%=;\n\t"                                                 \
            "D%=:\n\t}" :: "r"(_m), "r"(_p) : "memory");                       \
    }                                                                          \
} while (0)

#define LDSM4(r0, r1, r2, r3, a) \
    asm volatile("ldmatrix.sync.aligned.m8n8.x4.shared.b16 {%0,%1,%2,%3}, [%4];" \
                 : "=r"(r0), "=r"(r1), "=r"(r2), "=r"(r3) : "r"(a))

#define MMA16816(d, a0, a1, a2, a3, b0, b1) \
    asm volatile("mma.sync.aligned.m16n8k16.row.col.f32.f16.f16.f32 " \
                 "{%0,%1,%2,%3}, {%4,%5,%6,%7}, {%8,%9}, {%0,%1,%2,%3};" \
                 : "+f"((d)[0]), "+f"((d)[1]), "+f"((d)[2]), "+f"((d)[3]) \
                 : "r"(a0), "r"(a1), "r"(a2), "r"(a3), "r"(b0), "r"(b1))

// ---------------------------------------------------------------------------
// W fp16 convert: 73728 float4s, 288 blocks x 256 thr.
// ---------------------------------------------------------------------------
__global__ __launch_bounds__(256) void wcvt_kernel(const float* __restrict__ w) {
    int i = blockIdx.x * 256 + threadIdx.x;
    int n = i / 192;
    int k = (i % 192) * 4;
    float4 v = *(const float4*)(w + (size_t)n * K_TOTAL + k);
    int c = k >> 5;
    int kin = k & 31;
    int phys = (kin >> 3) ^ ((n >> 1) & 3);
    uint32_t* dst = (uint32_t*)(g_wh + c * 12288 + n * 32 + phys * 8 + (kin & 7));
    dst[0] = pack2(v.x, v.y);
    dst[1] = pack2(v.z, v.w);
}

// ---------------------------------------------------------------------------
// Fused GEMM + bias + LayerNorm + entropy. Block = 32 M-rows, 256 thr, occ 2.
// 12 iterations of K=64 (2 same-channel chunks per iter, channel-interleaved:
// iter i -> channel i%3, chunk pair {8*(i%3)+2*(i/3), +1}).
// ---------------------------------------------------------------------------
__global__ __launch_bounds__(256, 2) void fused_kernel(
    const float* __restrict__ img, const float* __restrict__ bias,
    const float* __restrict__ gamma, const float* __restrict__ beta,
    float* __restrict__ out, float* __restrict__ ent) {
    extern __shared__ char smem[];
    const int bid = blockIdx.x;
    const int tid = threadIdx.x;
    const int wid = tid >> 5;
    const int lid = tid & 31;
    const int bm = bid;
    const uint32_t sbase = smem_u32(smem);
    const int qr = lid >> 2;
    const int qc = lid & 3;

    int* hist = (int*)(smem + SM_HIST);
    #pragma unroll
    for (int z = 0; z < 4; z++) hist[tid + 256 * z] = 0;
    if (tid < 32) {
        ((float*)(smem + SM_RSUM))[tid] = 0.0f;
        ((float*)(smem + SM_RSQ))[tid]  = 0.0f;
    }
    if (tid == 0) {
        // Stage s preloads iter s: chunk pair base = 8*(s%3) + 2*(s/3).
        #pragma unroll
        for (int s = 0; s < 2; s++) {
            MBAR_INIT(sbase + SM_MBAR + 8 * s, 1);
            MBAR_EXPECT_TX(sbase + SM_MBAR + 8 * s, B_IT_BYTES);
            BULK_CP(sbase + s * B_IT_BYTES,
                    (const char*)g_wh + (size_t)(8 * s) * 24576, B_IT_BYTES,
                    sbase + SM_MBAR + 8 * s);
        }
    }

    // A gather geometry: 2 float4s per thread per iter (rows 0..31 x 8 slots).
    const int arow = tid >> 3;
    const int aj = tid & 7;
    const float* abase;
    {
        int m = bm * M_CTA + arow;
        abase = img + (size_t)((m / NPATCH) * 3) * CHAN_STRIDE
              + (size_t)(((m % NPATCH) / GRID_HW) * 16) * IMG_HW
              + ((m % NPATCH) % GRID_HW) * 16;
    }
    const uint32_t adst = arow * 64 + (((aj >> 1) ^ ((arow >> 1) & 3)) << 4)
                        + (aj & 1) * 8;
    // (ph, grp) -> image offset of this thread's float4 in that chunk
    auto aoff = [&](int ph, int grp) -> size_t {
        int pix = grp * 32 + 4 * aj;
        return (size_t)ph * CHAN_STRIDE + (pix >> 4) * IMG_HW + (pix & 15);
    };

    // Prologue: iter0 (ch0, grps 0,1) -> A buf 0; iter1 (ch1, grps 0,1) -> regs.
    float4 carry0, carry1, areg0, areg1;
    {
        float4 v0 = *(const float4*)(abase + aoff(0, 0));
        float4 v1 = *(const float4*)(abase + aoff(0, 1));
        *(uint2*)(smem + SM_A0 + adst) =
            make_uint2(pack2(v0.x, v0.y), pack2(v0.z, v0.w));
        *(uint2*)(smem + SM_A0 + 2048 + adst) =
            make_uint2(pack2(v1.x, v1.y), pack2(v1.z, v1.w));
        carry0 = v0; carry1 = v1;
        areg0 = *(const float4*)(abase + aoff(1, 0));
        areg1 = *(const float4*)(abase + aoff(1, 1));
    }
    __syncthreads();

    float acc[48];
    #pragma unroll
    for (int i = 0; i < 48; i++) acc[i] = 0.0f;

    // lane geometry (ldmatrix)
    const int a_row = ((lid >> 3) & 1) * 8 + (lid & 7);
    const int a_kbit = lid >> 4;
    const int b_noff = ((lid >> 4) & 1) * 8 + (lid & 7);
    const int b_segbit = (lid >> 3) & 1;
    const int xr = (lid & 7) >> 1;

    for (int i = 0; i < NITER; i++) {
        const int s = i & 1;
        MBAR_WAIT(sbase + SM_MBAR + 8 * s, (i >> 1) & 1);

        // Store A(i+1) + entropy step (j = i+1); prefetch A(i+2).
        if (i + 1 < NITER) {
            char* Ab = smem + SM_A0 + ((i + 1) & 1) * A_IT_BYTES;
            *(uint2*)(Ab + adst) =
                make_uint2(pack2(areg0.x, areg0.y), pack2(areg0.z, areg0.w));
            *(uint2*)(Ab + 2048 + adst) =
                make_uint2(pack2(areg1.x, areg1.y), pack2(areg1.z, areg1.w));
            const int jph = (i + 1) % 3;
            if (jph == 0) {
                carry0 = areg0; carry1 = areg1;
            } else if (jph == 1) {
                carry0.x += areg0.x; carry0.y += areg0.y;
                carry0.z += areg0.z; carry0.w += areg0.w;
                carry1.x += areg1.x; carry1.y += areg1.y;
                carry1.z += areg1.z; carry1.w += areg1.w;
            } else {
                int* hrow = hist + arow * 32;
                float g0 = (carry0.x + areg0.x) * (1.0f / 3.0f);
                float g1 = (carry0.y + areg0.y) * (1.0f / 3.0f);
                float g2 = (carry0.z + areg0.z) * (1.0f / 3.0f);
                float g3 = (carry0.w + areg0.w) * (1.0f / 3.0f);
                atomicAdd(hrow + (int)fminf(fmaxf(g0 * 31.0f, 0.0f), 31.0f), 1);
                atomicAdd(hrow + (int)fminf(fmaxf(g1 * 31.0f, 0.0f), 31.0f), 1);
                atomicAdd(hrow + (int)fminf(fmaxf(g2 * 31.0f, 0.0f), 31.0f), 1);
                atomicAdd(hrow + (int)fminf(fmaxf(g3 * 31.0f, 0.0f), 31.0f), 1);
                float h0 = (carry1.x + areg1.x) * (1.0f / 3.0f);
                float h1 = (carry1.y + areg1.y) * (1.0f / 3.0f);
                float h2 = (carry1.z + areg1.z) * (1.0f / 3.0f);
                float h3 = (carry1.w + areg1.w) * (1.0f / 3.0f);
                atomicAdd(hrow + (int)fminf(fmaxf(h0 * 31.0f, 0.0f), 31.0f), 1);
                atomicAdd(hrow + (int)fminf(fmaxf(h1 * 31.0f, 0.0f), 31.0f), 1);
                atomicAdd(hrow + (int)fminf(fmaxf(h2 * 31.0f, 0.0f), 31.0f), 1);
                atomicAdd(hrow + (int)fminf(fmaxf(h3 * 31.0f, 0.0f), 31.0f), 1);
            }
            if (i + 2 < NITER) {
                const int ph = (i + 2) % 3;
                const int t2 = (i + 2) / 3;
                areg0 = *(const float4*)(abase + aoff(ph, 2 * t2));
                areg1 = *(const float4*)(abase + aoff(ph, 2 * t2 + 1));
            }
        }

        const uint32_t Bst = sbase + s * B_IT_BYTES;
        const uint32_t Ast = sbase + SM_A0 + (i & 1) * A_IT_BYTES;
        #pragma unroll
        for (int sh = 0; sh < 4; sh++) {
            const uint32_t Bsh = Bst + (sh >> 1) * 24576;
            const uint32_t Ash = Ast + (sh >> 1) * 2048;
            uint32_t bf[3][4];
            const int sg = (2 * (sh & 1) + b_segbit) ^ xr;
            #pragma unroll
            for (int tp = 0; tp < 3; tp++) {
                int n = 48 * wid + 16 * tp + b_noff;
                LDSM4(bf[tp][0], bf[tp][1], bf[tp][2], bf[tp][3],
                      Bsh + n * 64 + sg * 16);
            }
            const int aseg = (2 * (sh & 1) + a_kbit) ^ xr;
            #pragma unroll
            for (int ii = 0; ii < 2; ii++) {
                uint32_t a0, a1, a2, a3;
                LDSM4(a0, a1, a2, a3, Ash + (16 * ii + a_row) * 64 + aseg * 16);
                #pragma unroll
                for (int tp = 0; tp < 3; tp++) {
                    MMA16816(acc + (ii * 6 + 2 * tp) * 4, a0, a1, a2, a3,
                             bf[tp][0], bf[tp][1]);
                    MMA16816(acc + (ii * 6 + 2 * tp + 1) * 4, a0, a1, a2, a3,
                             bf[tp][2], bf[tp][3]);
                }
            }
        }
        __syncthreads();
        // Refill stage s for iter i+2.
        if (tid == 0 && i + 2 < NITER) {
            const int cbase = 8 * ((i + 2) % 3) + 2 * ((i + 2) / 3);
            MBAR_EXPECT_TX(sbase + SM_MBAR + 8 * s, B_IT_BYTES);
            BULK_CP(sbase + s * B_IT_BYTES,
                    (const char*)g_wh + (size_t)cbase * 24576, B_IT_BYTES,
                    sbase + SM_MBAR + 8 * s);
        }
    }

    // ---------------- fused LayerNorm epilogue ----------------
    float* rsum = (float*)(smem + SM_RSUM);
    float* rsq  = (float*)(smem + SM_RSQ);

    float2 bs2[6];
    #pragma unroll
    for (int t = 0; t < 6; t++)
        bs2[t] = *(const float2*)&bias[48 * wid + 8 * t + 2 * qc];

    #pragma unroll
    for (int i = 0; i < 2; i++) {
        float s0 = 0, q0 = 0, s1 = 0, q1 = 0;
        #pragma unroll
        for (int t = 0; t < 6; t++) {
            float* d = acc + (i * 6 + t) * 4;
            d[0] += bs2[t].x; d[1] += bs2[t].y;
            d[2] += bs2[t].x; d[3] += bs2[t].y;
            s0 += d[0] + d[1]; q0 += d[0] * d[0] + d[1] * d[1];
            s1 += d[2] + d[3]; q1 += d[2] * d[2] + d[3] * d[3];
        }
        #pragma unroll
        for (int o = 1; o <= 2; o <<= 1) {
            s0 += __shfl_xor_sync(0xffffffffu, s0, o);
            q0 += __shfl_xor_sync(0xffffffffu, q0, o);
            s1 += __shfl_xor_sync(0xffffffffu, s1, o);
            q1 += __shfl_xor_sync(0xffffffffu, q1, o);
        }
        if (qc == 0) {
            atomicAdd(&rsum[16 * i + qr], s0);
            atomicAdd(&rsq[16 * i + qr], q0);
            atomicAdd(&rsum[16 * i + qr + 8], s1);
            atomicAdd(&rsq[16 * i + qr + 8], q1);
        }
    }
    __syncthreads();

    // Entropy reduction: 8 warps x 4 rows; lane = bin.
    #pragma unroll
    for (int rr = 0; rr < 4; rr++) {
        const int r = wid * 4 + rr;
        float p = (float)hist[r * 32 + lid] * (1.0f / 256.0f);
        float t = p * log2f(p + 1e-10f);
        #pragma unroll
        for (int o = 16; o; o >>= 1) t += __shfl_xor_sync(0xffffffffu, t, o);
        if (lid == 0) ent[bm * M_CTA + r] = -t * 0.2f;
    }

    float* smu = (float*)(smem + SM_MU);
    float* srs = (float*)(smem + SM_RS);
    if (tid < 32) {
        float mu = rsum[tid] * (1.0f / EMBED);
        float vv = rsq[tid] * (1.0f / EMBED) - mu * mu;
        smu[tid] = mu;
        srs[tid] = rsqrtf(fmaxf(vv, 0.0f) + 1e-5f);
    }
    __syncthreads();

    float2 g2[6], be2[6];
    #pragma unroll
    for (int t = 0; t < 6; t++) {
        g2[t]  = *(const float2*)&gamma[48 * wid + 8 * t + 2 * qc];
        be2[t] = *(const float2*)&beta[48 * wid + 8 * t + 2 * qc];
    }

    #pragma unroll
    for (int i = 0; i < 2; i++) {
        const int r0 = 16 * i + qr;
        const float mu0 = smu[r0], rs0 = srs[r0];
        const float mu1 = smu[r0 + 8], rs1 = srs[r0 + 8];
        float* o0 = out + (size_t)(bm * M_CTA + r0) * EMBED + 48 * wid + 2 * qc;
        float* o1 = o0 + 8 * (size_t)EMBED;
        #pragma unroll
        for (int t = 0; t < 6; t++) {
            float* d = acc + (i * 6 + t) * 4;
            float2 w0, w1;
            w0.x = (d[0] - mu0) * rs0 * g2[t].x + be2[t].x;
            w0.y = (d[1] - mu0) * rs0 * g2[t].y + be2[t].y;
            w1.x = (d[2] - mu1) * rs1 * g2[t].x + be2[t].x;
            w1.y = (d[3] - mu1) * rs1 * g2[t].y + be2[t].y;
            *(float2*)(o0 + 8 * t) = w0;
            *(float2*)(o1 + 8 * t) = w1;
        }
    }
}

// ---------------------------------------------------------------------------
extern "C" void kernel_launch(void* const* d_in, const int* in_sizes, int n_in,
                              void* d_out, int out_size) {
    const float* images = (const float*)d_in[0];
    const float* proj_w = (const float*)d_in[1];
    const float* proj_b = (const float*)d_in[2];
    const float* ln_g   = (const float*)d_in[3];
    const float* ln_b   = (const float*)d_in[4];
    float* out = (float*)d_out;

    float* x   = out;
    float* ent = out + (size_t)M_TOTAL * EMBED;

    cudaFuncSetAttribute(fused_kernel,
                         cudaFuncAttributeMaxDynamicSharedMemorySize, SMEM_TOTAL);

    wcvt_kernel<<<288, 256>>>(proj_w);
    fused_kernel<<<G_CTAS, 256, SMEM_TOTAL>>>(images, proj_b, ln_g, ln_b, x, ent);
}